// round 5
// baseline (speedup 1.0000x reference)
#include <cuda_runtime.h>
#include <math.h>

#define BB 16
#define DD 256
#define LL 200
#define TT 1000

// output layout (float32, flattened concat of reference tuple)
#define LS_OFF   4096000
#define FM_OFF   8192000
#define FL_OFF   8208000
#define W_OFF    8208016

#define NEG_INF (__int_as_float(0xff800000))

// -------- scratch (device globals; no allocations allowed) --------
__device__ float g_sk[BB*LL];
__device__ int   g_flen[BB];
__device__ float g_CW[2*8*3*DD];      // [path][o][k][d]
__device__ float g_bk[2*8*3];         // per-tap bias const
__device__ float g_h[2*BB*LL*8];      // [path][b][l][o]
__device__ float g_phT[BB*LL*DD];     // phoneme transposed [b][l][d]
__device__ float g_P[BB*LL*4*DD];     // [b][l][q][e]
__device__ float g_Wscr[BB*TT*LL*4];  // [b][t][l*4+q]
__device__ float g_part[BB*TT*DD];    // lbw+lbc + wc@Lc
__device__ float g_whc[BB*TT*DD];

__device__ __forceinline__ float siluf(float x) { return x / (1.f + __expf(-x)); }

// ---------------- K1: scan durations, frame lengths/mask ----------------
__global__ void k_setup(const float* __restrict__ dur, float* __restrict__ out) {
    int b = blockIdx.x, tid = threadIdx.x;
    __shared__ float s[256];
    __shared__ double ds[256];
    __shared__ int sfl;
    float d = (tid < LL) ? dur[b*LL + tid] : 0.f;
    s[tid] = d;
    for (int off = 1; off < 256; off <<= 1) {
        __syncthreads();
        float v = (tid >= off) ? s[tid - off] : 0.f;
        __syncthreads();
        s[tid] += v;
    }
    __syncthreads();
    if (tid < LL) g_sk[b*LL + tid] = s[tid] - d;   // exclusive cumsum
    ds[tid] = (double)d;
    __syncthreads();
    for (int off = 128; off > 0; off >>= 1) {
        if (tid < off) ds[tid] += ds[tid + off];
        __syncthreads();
    }
    if (tid == 0) {
        int fl = (int)rint(ds[0]);
        if (fl < 0) fl = 0;
        if (fl > TT) fl = TT;
        g_flen[b] = fl;
        out[FL_OFF + b] = (float)fl;
        sfl = fl;
    }
    __syncthreads();
    int fl = sfl;
    for (int t = tid; t < TT; t += 256)
        out[FM_OFF + b*TT + t] = (t < fl) ? 1.f : 0.f;
}

// ---------------- K2: fold conv kernels with pointwise weight ----------------
__global__ void k_fold(const float* __restrict__ Cw, const float* __restrict__ Wpw,
                       const float* __restrict__ bpw, const float* __restrict__ Cc,
                       const float* __restrict__ Wpc, const float* __restrict__ bpc) {
    int blk = blockIdx.x;              // 48 blocks: p*24 + o*3 + k
    int p = blk / 24, r = blk % 24, o = r / 3, k = r % 3;
    const float* Cm = p ? Cc : Cw;
    const float* Wp = p ? Wpc : Wpw;
    const float* bp = p ? bpc : bpw;
    int dp = threadIdx.x;
    float s = 0.f;
    for (int d = 0; d < DD; d++)
        s += Cm[(o*DD + d)*3 + k] * Wp[d*DD + dp];
    g_CW[((p*8 + o)*3 + k)*DD + dp] = s;
    if (dp == 0) {
        float bs = 0.f;
        for (int d = 0; d < DD; d++) bs += Cm[(o*DD + d)*3 + k] * bp[d];
        g_bk[(p*8 + o)*3 + k] = bs;
    }
}

// ---------------- K3: h_w / h_c (folded conv + silu + mask) ----------------
__global__ void k_conv(const float* __restrict__ ph, const float* __restrict__ dur,
                       const float* __restrict__ cbw, const float* __restrict__ cbc) {
    int bl = blockIdx.x;
    int b = bl / LL, l = bl % LL;
    __shared__ float sph[3*DD];
    int tid = threadIdx.x;
    for (int i = tid; i < 3*DD; i += 512) {
        int k = i / DD, d = i % DD;
        int ll = l + k - 1;
        sph[i] = (ll >= 0 && ll < LL) ? ph[(b*DD + d)*LL + ll] : 0.f;
    }
    __syncthreads();
    int wid = tid / 32, lane = tid % 32;   // wid = p*8+o
    float s = 0.f;
    const float* cw = &g_CW[wid*3*DD];
    for (int i = lane; i < 3*DD; i += 32) s += cw[i] * sph[i];
    #pragma unroll
    for (int off = 16; off > 0; off >>= 1) s += __shfl_down_sync(0xffffffffu, s, off);
    if (lane == 0) {
        int p = wid / 8, o = wid % 8;
        float bias = p ? cbc[o] : cbw[o];
        #pragma unroll
        for (int k = 0; k < 3; k++) {
            int ll = l + k - 1;
            if (ll >= 0 && ll < LL) bias += g_bk[wid*3 + k];
        }
        float h = siluf(s + bias);
        bool pm = dur[b*LL + l] > 0.f;
        g_h[((p*BB + b)*LL + l)*8 + o] = pm ? h : 0.f;
    }
}

// ---------------- K4t: transpose phoneme to [b][l][d] ----------------
__global__ void k_transpose(const float* __restrict__ ph) {
    __shared__ float tile[32][33];
    int b = blockIdx.z;
    int l0 = blockIdx.x * 32, d0 = blockIdx.y * 32;
    int tx = threadIdx.x, ty = threadIdx.y;
    #pragma unroll
    for (int j = 0; j < 32; j += 8) {
        int d = d0 + ty + j, l = l0 + tx;
        tile[ty + j][tx] = (l < LL) ? ph[(b*DD + d)*LL + l] : 0.f;
    }
    __syncthreads();
    #pragma unroll
    for (int j = 0; j < 32; j += 8) {
        int l = l0 + ty + j, d = d0 + tx;
        if (l < LL) g_phT[(b*LL + l)*DD + d] = tile[tx][ty + j];
    }
}

// ---------------- K4: P[b,l,q,e] = phT @ Lw_q  (3200 x 256 x 256, x4 q) ----------------
__global__ void k_gemm_P(const float* __restrict__ Lw) {
    int nt = blockIdx.x, mt = blockIdx.y, q = blockIdx.z;
    int m0 = mt*64, n0 = nt*64;
    const float* A  = g_phT;
    const float* Bm = Lw + q*DD*DD;
    __shared__ float As[16*64], Bs[16*64];
    int tid = threadIdx.x;
    int ty = tid / 16, tx = tid % 16;
    int arow = tid / 4, akq = tid % 4;
    int brow = tid / 16, bnq = tid % 16;
    float acc[4][4] = {};
    for (int k0 = 0; k0 < DD; k0 += 16) {
        float4 a4 = *(const float4*)&A[(m0 + arow)*DD + k0 + akq*4];
        float4 b4 = *(const float4*)&Bm[(k0 + brow)*DD + n0 + bnq*4];
        As[(akq*4+0)*64 + arow] = a4.x;
        As[(akq*4+1)*64 + arow] = a4.y;
        As[(akq*4+2)*64 + arow] = a4.z;
        As[(akq*4+3)*64 + arow] = a4.w;
        *(float4*)&Bs[brow*64 + bnq*4] = b4;
        __syncthreads();
        #pragma unroll
        for (int kk = 0; kk < 16; kk++) {
            float av[4], bv[4];
            *(float4*)av = *(const float4*)&As[kk*64 + ty*4];
            *(float4*)bv = *(const float4*)&Bs[kk*64 + tx*4];
            #pragma unroll
            for (int i = 0; i < 4; i++)
                #pragma unroll
                for (int j = 0; j < 4; j++) acc[i][j] += av[i]*bv[j];
        }
        __syncthreads();
    }
    #pragma unroll
    for (int i = 0; i < 4; i++) {
        int m = m0 + ty*4 + i;
        #pragma unroll
        for (int j = 0; j < 4; j++)
            g_P[(m*4 + q)*DD + n0 + tx*4 + j] = acc[i][j];
    }
}

// ---------------- K5a: MLPs + softmax + w outputs + small-path ----------------
__global__ void k_wsoft(const float* __restrict__ dur,
                        const float* __restrict__ Mw, const float* __restrict__ mbw,
                        const float* __restrict__ Mc, const float* __restrict__ mbc,
                        const float* __restrict__ Lc,
                        const float* __restrict__ lbw, const float* __restrict__ lbc,
                        float* __restrict__ out) {
    int t = blockIdx.x, b = blockIdx.y;
    int tid = threadIdx.x;
    float* w_out = out + W_OFF;
    int fl = g_flen[b];
    if (t >= fl) {
        for (int i = tid; i < 4*LL; i += 256) {
            int q = i / LL, l = i % LL;
            w_out[(((size_t)b*4 + q)*TT + t)*LL + l] = 0.f;
        }
        return;
    }
    __shared__ float s_arr[4*256];
    __shared__ float s_c[2*256];
    __shared__ float s_part[8*8];
    __shared__ float s_max[4], s_sum[4], s_wc[8];

    float lw[4], cc[2];
    bool valid = tid < LL;
    if (valid) {
        float d = dur[b*LL + tid];
        bool pm = d > 0.f;
        float sk = g_sk[b*LL + tid];
        float S = pm ? (float)(t + 1) - sk : 0.f;
        float E = pm ? d : 0.f;
        const float* hwp = &g_h[((0*BB + b)*LL + tid)*8];
        const float* hcp = &g_h[((1*BB + b)*LL + tid)*8];
        #pragma unroll
        for (int q = 0; q < 4; q++) {
            float a = mbw[q] + S*Mw[0*4+q] + E*Mw[1*4+q];
            #pragma unroll
            for (int o = 0; o < 8; o++) a += hwp[o]*Mw[(2+o)*4 + q];
            float v = siluf(a);
            lw[q] = pm ? v : NEG_INF;
        }
        #pragma unroll
        for (int p = 0; p < 2; p++) {
            float a = mbc[p] + S*Mc[0*2+p] + E*Mc[1*2+p];
            #pragma unroll
            for (int o = 0; o < 8; o++) a += hcp[o]*Mc[(2+o)*2 + p];
            cc[p] = siluf(a);
        }
    } else {
        lw[0] = lw[1] = lw[2] = lw[3] = NEG_INF;
        cc[0] = cc[1] = 0.f;
    }
    #pragma unroll
    for (int q = 0; q < 4; q++) s_arr[q*256 + tid] = lw[q];
    __syncthreads();
    int wid = tid / 32, lane = tid % 32;
    if (wid < 4) {
        float m = NEG_INF;
        for (int i = lane; i < 256; i += 32) m = fmaxf(m, s_arr[wid*256 + i]);
        #pragma unroll
        for (int off = 16; off > 0; off >>= 1) m = fmaxf(m, __shfl_down_sync(0xffffffffu, m, off));
        if (lane == 0) s_max[wid] = m;
    }
    __syncthreads();
    float ex[4];
    #pragma unroll
    for (int q = 0; q < 4; q++) {
        ex[q] = __expf(lw[q] - s_max[q]);
        s_arr[q*256 + tid] = ex[q];
    }
    __syncthreads();
    if (wid < 4) {
        float sm = 0.f;
        for (int i = lane; i < 256; i += 32) sm += s_arr[wid*256 + i];
        #pragma unroll
        for (int off = 16; off > 0; off >>= 1) sm += __shfl_down_sync(0xffffffffu, sm, off);
        if (lane == 0) s_sum[wid] = sm;
    }
    __syncthreads();
    float wq[4];
    #pragma unroll
    for (int q = 0; q < 4; q++) wq[q] = ex[q] / s_sum[q];
    if (valid) {
        #pragma unroll
        for (int q = 0; q < 4; q++)
            w_out[(((size_t)b*4 + q)*TT + t)*LL + tid] = wq[q];
        float4 v = make_float4(wq[0], wq[1], wq[2], wq[3]);
        *(float4*)&g_Wscr[((size_t)b*TT + t)*800 + tid*4] = v;
    }
    // wc[q][p] reductions
    float prod[8];
    #pragma unroll
    for (int q = 0; q < 4; q++)
        #pragma unroll
        for (int p = 0; p < 2; p++) prod[q*2+p] = wq[q]*cc[p];
    #pragma unroll
    for (int j = 0; j < 8; j++) {
        float v = prod[j];
        #pragma unroll
        for (int off = 16; off > 0; off >>= 1) v += __shfl_down_sync(0xffffffffu, v, off);
        if (lane == 0) s_part[wid*8 + j] = v;
    }
    __syncthreads();
    if (tid < 8) {
        float s = 0.f;
        #pragma unroll
        for (int w = 0; w < 8; w++) s += s_part[w*8 + tid];
        s_wc[tid] = s;
    }
    __syncthreads();
    float acc = lbw[tid] + lbc[tid];
    #pragma unroll
    for (int qp = 0; qp < 8; qp++) acc += s_wc[qp]*Lc[qp*DD + tid];
    g_part[((size_t)b*TT + t)*DD + tid] = acc;
}

// ---------------- K5b: whc[t,e] = W(1000x800) @ P_b(800x256) + part, masked ----------------
__global__ void k_gemm_whc() {
    int nt = blockIdx.x, mt = blockIdx.y, b = blockIdx.z;
    int m0 = mt*64, n0 = nt*64;
    const float* A  = g_Wscr + (size_t)b*TT*800;
    const float* Bm = g_P + (size_t)b*LL*4*DD;
    __shared__ float As[16*64], Bs[16*64];
    int tid = threadIdx.x;
    int ty = tid / 16, tx = tid % 16;
    int arow = tid / 4, akq = tid % 4;
    int brow = tid / 16, bnq = tid % 16;
    float acc[4][4] = {};
    for (int k0 = 0; k0 < 800; k0 += 16) {
        int am = m0 + arow;
        float4 a4 = make_float4(0.f, 0.f, 0.f, 0.f);
        if (am < TT) a4 = *(const float4*)&A[(size_t)am*800 + k0 + akq*4];
        float4 b4 = *(const float4*)&Bm[(k0 + brow)*DD + n0 + bnq*4];
        As[(akq*4+0)*64 + arow] = a4.x;
        As[(akq*4+1)*64 + arow] = a4.y;
        As[(akq*4+2)*64 + arow] = a4.z;
        As[(akq*4+3)*64 + arow] = a4.w;
        *(float4*)&Bs[brow*64 + bnq*4] = b4;
        __syncthreads();
        #pragma unroll
        for (int kk = 0; kk < 16; kk++) {
            float av[4], bv[4];
            *(float4*)av = *(const float4*)&As[kk*64 + ty*4];
            *(float4*)bv = *(const float4*)&Bs[kk*64 + tx*4];
            #pragma unroll
            for (int i = 0; i < 4; i++)
                #pragma unroll
                for (int j = 0; j < 4; j++) acc[i][j] += av[i]*bv[j];
        }
        __syncthreads();
    }
    int fl = g_flen[b];
    #pragma unroll
    for (int i = 0; i < 4; i++) {
        int m = m0 + ty*4 + i;
        if (m < TT) {
            #pragma unroll
            for (int j = 0; j < 4; j++) {
                int e = n0 + tx*4 + j;
                float v = (m < fl) ? acc[i][j] + g_part[((size_t)b*TT + m)*DD + e] : 0.f;
                g_whc[((size_t)b*TT + m)*DD + e] = v;
            }
        }
    }
}

// ---------------- K5c: out = whc(16000x256) @ Wo(256x512) + bo, transposed write ----------------
__global__ void k_gemm_out(const float* __restrict__ Wo, const float* __restrict__ bo,
                           float* __restrict__ out) {
    int nt = blockIdx.x, mt = blockIdx.y;
    int m0 = mt*64, n0 = nt*64;
    const float* A = g_whc;
    __shared__ float As[16*64], Bs[16*64];
    int tid = threadIdx.x;
    int ty = tid / 16, tx = tid % 16;
    int arow = tid / 4, akq = tid % 4;
    int brow = tid / 16, bnq = tid % 16;
    float acc[4][4] = {};
    for (int k0 = 0; k0 < DD; k0 += 16) {
        float4 a4 = *(const float4*)&A[((size_t)m0 + arow)*DD + k0 + akq*4];
        float4 b4 = *(const float4*)&Wo[(k0 + brow)*512 + n0 + bnq*4];
        As[(akq*4+0)*64 + arow] = a4.x;
        As[(akq*4+1)*64 + arow] = a4.y;
        As[(akq*4+2)*64 + arow] = a4.z;
        As[(akq*4+3)*64 + arow] = a4.w;
        *(float4*)&Bs[brow*64 + bnq*4] = b4;
        __syncthreads();
        #pragma unroll
        for (int kk = 0; kk < 16; kk++) {
            float av[4], bv[4];
            *(float4*)av = *(const float4*)&As[kk*64 + ty*4];
            *(float4*)bv = *(const float4*)&Bs[kk*64 + tx*4];
            #pragma unroll
            for (int i = 0; i < 4; i++)
                #pragma unroll
                for (int j = 0; j < 4; j++) acc[i][j] += av[i]*bv[j];
        }
        __syncthreads();
    }
    #pragma unroll
    for (int j = 0; j < 4; j++) {
        int o = n0 + tx*4 + j;
        float bj = bo[o];
        #pragma unroll
        for (int i = 0; i < 4; i++) {
            int m = m0 + ty*4 + i;
            int b = m / TT, t = m % TT;
            float v = acc[i][j] + bj;
            if (o < 256)
                out[((size_t)b*256 + o)*TT + t] = v;
            else
                out[LS_OFF + ((size_t)b*256 + (o - 256))*TT + t] = v;
        }
    }
}

extern "C" void kernel_launch(void* const* d_in, const int* in_sizes, int n_in,
                              void* d_out, int out_size) {
    const float* dur = (const float*)d_in[0];
    const float* ph  = (const float*)d_in[1];
    const float* Wpw = (const float*)d_in[3];
    const float* bpw = (const float*)d_in[4];
    const float* Cw  = (const float*)d_in[5];
    const float* cbw = (const float*)d_in[6];
    const float* Mw  = (const float*)d_in[7];
    const float* mbw = (const float*)d_in[8];
    const float* Lw  = (const float*)d_in[9];
    const float* lbw = (const float*)d_in[10];
    const float* Wpc = (const float*)d_in[11];
    const float* bpc = (const float*)d_in[12];
    const float* Cc  = (const float*)d_in[13];
    const float* cbc = (const float*)d_in[14];
    const float* Mc  = (const float*)d_in[15];
    const float* mbc = (const float*)d_in[16];
    const float* Lc  = (const float*)d_in[17];
    const float* lbc = (const float*)d_in[18];
    const float* Wo  = (const float*)d_in[19];
    const float* bo  = (const float*)d_in[20];
    float* out = (float*)d_out;

    k_setup<<<BB, 256>>>(dur, out);
    k_fold<<<48, 256>>>(Cw, Wpw, bpw, Cc, Wpc, bpc);
    k_conv<<<BB*LL, 512>>>(ph, dur, cbw, cbc);
    k_transpose<<<dim3(7, 8, BB), dim3(32, 8)>>>(ph);
    k_gemm_P<<<dim3(4, 50, 4), 256>>>(Lw);
    k_wsoft<<<dim3(TT, BB), 256>>>(dur, Mw, mbw, Mc, mbc, Lc, lbw, lbc, out);
    k_gemm_whc<<<dim3(4, 16, BB), 256>>>();
    k_gemm_out<<<dim3(8, 250), 256>>>(Wo, bo, out);
}

// round 7
// speedup vs baseline: 1.1739x; 1.1739x over previous
#include <cuda_runtime.h>
#include <math.h>
#include <stdint.h>

#define BB 16
#define DD 256
#define LL 200
#define TT 1000

// output layout (float32, flattened concat of reference tuple)
#define LS_OFF   4096000
#define FM_OFF   8192000
#define FL_OFF   8208000
#define W_OFF    8208016

#define NEG_INF (__int_as_float(0xff800000))

// -------- scratch (device globals; no allocations allowed) --------
__device__ float  g_sk[BB*LL];
__device__ int    g_flen[BB];
__device__ float  g_CW[2*8*3*DD];
__device__ float  g_bk[2*8*3];
__device__ float  g_h[2*BB*LL*8];      // [path][b][l][o]
__device__ float4 g_bw4[BB*LL];        // MLP-w base per (b,l)
__device__ float2 g_bc2[BB*LL];        // MLP-c base per (b,l)
__device__ float  g_phT[BB*LL*DD];     // [b*l][d]
__device__ float  g_P[BB*LL*4*DD];     // [b][l][q][e]
__device__ float  g_Wscr[BB*TT*LL*4];  // [b][t][l*4+q]  (zero-init; rows >= fl never written)
__device__ float  g_part[BB*TT*DD];
__device__ float  g_whc[BB*TT*DD];

__device__ __forceinline__ float siluf(float x) { return x / (1.f + __expf(-x)); }

__device__ __forceinline__ void unpack2(unsigned long long v, float& lo, float& hi) {
    uint32_t a, b;
    asm("mov.b64 {%0, %1}, %2;" : "=r"(a), "=r"(b) : "l"(v));
    lo = __uint_as_float(a); hi = __uint_as_float(b);
}

// 16-step K inner product on a 64x64 tile, per-thread 4x4 accumulators held as
// f32x2 pairs over N. 8 packed FFMA2 + 4 packs per step (vs 16 scalar FFMA).
__device__ __forceinline__ void tile_mma16(const float* As, const float* Bs,
        int ty, int tx, unsigned long long (&accp)[4][2]) {
    #pragma unroll
    for (int kk = 0; kk < 16; kk++) {
        uint4 a4 = *(const uint4*)&As[kk*64 + ty*4];
        ulonglong2 bp = *(const ulonglong2*)&Bs[kk*64 + tx*4];
        unsigned long long ap;
        asm("mov.b64 %0, {%1, %1};" : "=l"(ap) : "r"(a4.x));
        asm("fma.rn.f32x2 %0, %1, %2, %0;" : "+l"(accp[0][0]) : "l"(ap), "l"(bp.x));
        asm("fma.rn.f32x2 %0, %1, %2, %0;" : "+l"(accp[0][1]) : "l"(ap), "l"(bp.y));
        asm("mov.b64 %0, {%1, %1};" : "=l"(ap) : "r"(a4.y));
        asm("fma.rn.f32x2 %0, %1, %2, %0;" : "+l"(accp[1][0]) : "l"(ap), "l"(bp.x));
        asm("fma.rn.f32x2 %0, %1, %2, %0;" : "+l"(accp[1][1]) : "l"(ap), "l"(bp.y));
        asm("mov.b64 %0, {%1, %1};" : "=l"(ap) : "r"(a4.z));
        asm("fma.rn.f32x2 %0, %1, %2, %0;" : "+l"(accp[2][0]) : "l"(ap), "l"(bp.x));
        asm("fma.rn.f32x2 %0, %1, %2, %0;" : "+l"(accp[2][1]) : "l"(ap), "l"(bp.y));
        asm("mov.b64 %0, {%1, %1};" : "=l"(ap) : "r"(a4.w));
        asm("fma.rn.f32x2 %0, %1, %2, %0;" : "+l"(accp[3][0]) : "l"(ap), "l"(bp.x));
        asm("fma.rn.f32x2 %0, %1, %2, %0;" : "+l"(accp[3][1]) : "l"(ap), "l"(bp.y));
    }
}

// ---------------- K1: scan durations, frame lengths/mask ----------------
__global__ void k_setup(const float* __restrict__ dur, float* __restrict__ out) {
    int b = blockIdx.x, tid = threadIdx.x;
    __shared__ float s[256];
    __shared__ double ds[256];
    __shared__ int sfl;
    float d = (tid < LL) ? dur[b*LL + tid] : 0.f;
    s[tid] = d;
    for (int off = 1; off < 256; off <<= 1) {
        __syncthreads();
        float v = (tid >= off) ? s[tid - off] : 0.f;
        __syncthreads();
        s[tid] += v;
    }
    __syncthreads();
    if (tid < LL) g_sk[b*LL + tid] = s[tid] - d;
    ds[tid] = (double)d;
    __syncthreads();
    for (int off = 128; off > 0; off >>= 1) {
        if (tid < off) ds[tid] += ds[tid + off];
        __syncthreads();
    }
    if (tid == 0) {
        int fl = (int)rint(ds[0]);
        if (fl < 0) fl = 0;
        if (fl > TT) fl = TT;
        g_flen[b] = fl;
        out[FL_OFF + b] = (float)fl;
        sfl = fl;
    }
    __syncthreads();
    int fl = sfl;
    for (int t = tid; t < TT; t += 256)
        out[FM_OFF + b*TT + t] = (t < fl) ? 1.f : 0.f;
}

// ---------------- K2: fold conv kernels with pointwise weight ----------------
__global__ void k_fold(const float* __restrict__ Cw, const float* __restrict__ Wpw,
                       const float* __restrict__ bpw, const float* __restrict__ Cc,
                       const float* __restrict__ Wpc, const float* __restrict__ bpc) {
    int blk = blockIdx.x;
    int p = blk / 24, r = blk % 24, o = r / 3, k = r % 3;
    const float* Cm = p ? Cc : Cw;
    const float* Wp = p ? Wpc : Wpw;
    const float* bp = p ? bpc : bpw;
    int dp = threadIdx.x;
    float s = 0.f;
    for (int d = 0; d < DD; d++)
        s += Cm[(o*DD + d)*3 + k] * Wp[d*DD + dp];
    g_CW[((p*8 + o)*3 + k)*DD + dp] = s;
    if (dp == 0) {
        float bs = 0.f;
        for (int d = 0; d < DD; d++) bs += Cm[(o*DD + d)*3 + k] * bp[d];
        g_bk[(p*8 + o)*3 + k] = bs;
    }
}

// ---------------- K3: h_w / h_c (folded conv + silu + mask) ----------------
__global__ void k_conv(const float* __restrict__ ph, const float* __restrict__ dur,
                       const float* __restrict__ cbw, const float* __restrict__ cbc) {
    int bl = blockIdx.x;
    int b = bl / LL, l = bl % LL;
    __shared__ float sph[3*DD];
    int tid = threadIdx.x;
    for (int i = tid; i < 3*DD; i += 512) {
        int k = i / DD, d = i % DD;
        int ll = l + k - 1;
        sph[i] = (ll >= 0 && ll < LL) ? ph[(b*DD + d)*LL + ll] : 0.f;
    }
    __syncthreads();
    int wid = tid / 32, lane = tid % 32;
    float s = 0.f;
    const float* cw = &g_CW[wid*3*DD];
    for (int i = lane; i < 3*DD; i += 32) s += cw[i] * sph[i];
    #pragma unroll
    for (int off = 16; off > 0; off >>= 1) s += __shfl_down_sync(0xffffffffu, s, off);
    if (lane == 0) {
        int p = wid / 8, o = wid % 8;
        float bias = p ? cbc[o] : cbw[o];
        #pragma unroll
        for (int k = 0; k < 3; k++) {
            int ll = l + k - 1;
            if (ll >= 0 && ll < LL) bias += g_bk[wid*3 + k];
        }
        float h = siluf(s + bias);
        bool pm = dur[b*LL + l] > 0.f;
        g_h[((p*BB + b)*LL + l)*8 + o] = pm ? h : 0.f;
    }
}

// ---------------- K3b: hoist per-(b,l) affine base of the MLPs ----------------
__global__ void k_base(const float* __restrict__ dur,
                       const float* __restrict__ Mw, const float* __restrict__ mbw,
                       const float* __restrict__ Mc, const float* __restrict__ mbc) {
    int b = blockIdx.x, l = threadIdx.x;
    if (l >= LL) return;
    float d  = dur[b*LL + l];
    float sk = g_sk[b*LL + l];
    const float* hw = &g_h[((0*BB + b)*LL + l)*8];
    const float* hc = &g_h[((1*BB + b)*LL + l)*8];
    float bw[4];
    #pragma unroll
    for (int q = 0; q < 4; q++) {
        float a = mbw[q] - sk*Mw[0*4+q] + d*Mw[1*4+q];
        #pragma unroll
        for (int o = 0; o < 8; o++) a += hw[o]*Mw[(2+o)*4 + q];
        bw[q] = a;
    }
    g_bw4[b*LL + l] = make_float4(bw[0], bw[1], bw[2], bw[3]);
    float bc[2];
    #pragma unroll
    for (int p = 0; p < 2; p++) {
        float a = mbc[p] - sk*Mc[0*2+p] + d*Mc[1*2+p];
        #pragma unroll
        for (int o = 0; o < 8; o++) a += hc[o]*Mc[(2+o)*2 + p];
        bc[p] = a;
    }
    g_bc2[b*LL + l] = make_float2(bc[0], bc[1]);
}

// ---------------- K4t: transpose phoneme to [b][l][d] ----------------
__global__ void k_transpose(const float* __restrict__ ph) {
    __shared__ float tile[32][33];
    int b = blockIdx.z;
    int l0 = blockIdx.x * 32, d0 = blockIdx.y * 32;
    int tx = threadIdx.x, ty = threadIdx.y;
    #pragma unroll
    for (int j = 0; j < 32; j += 8) {
        int d = d0 + ty + j, l = l0 + tx;
        tile[ty + j][tx] = (l < LL) ? ph[(b*DD + d)*LL + l] : 0.f;
    }
    __syncthreads();
    #pragma unroll
    for (int j = 0; j < 32; j += 8) {
        int l = l0 + ty + j, d = d0 + tx;
        if (l < LL) g_phT[(b*LL + l)*DD + d] = tile[tx][ty + j];
    }
}

// ---------------- K4: P[b,l,q,e] = phT @ Lw_q ----------------
__global__ void k_gemm_P(const float* __restrict__ Lw) {
    int nt = blockIdx.x, mt = blockIdx.y, q = blockIdx.z;
    int m0 = mt*64, n0 = nt*64;
    const float* A  = g_phT;
    const float* Bm = Lw + q*DD*DD;
    __shared__ float As[16*64], Bs[16*64];
    int tid = threadIdx.x;
    int ty = tid / 16, tx = tid % 16;
    int arow = tid / 4, akq = tid % 4;
    int brow = tid / 16, bnq = tid % 16;
    unsigned long long accp[4][2] = {};
    for (int k0 = 0; k0 < DD; k0 += 16) {
        float4 a4 = *(const float4*)&A[(m0 + arow)*DD + k0 + akq*4];
        float4 b4 = *(const float4*)&Bm[(k0 + brow)*DD + n0 + bnq*4];
        As[(akq*4+0)*64 + arow] = a4.x;
        As[(akq*4+1)*64 + arow] = a4.y;
        As[(akq*4+2)*64 + arow] = a4.z;
        As[(akq*4+3)*64 + arow] = a4.w;
        *(float4*)&Bs[brow*64 + bnq*4] = b4;
        __syncthreads();
        tile_mma16(As, Bs, ty, tx, accp);
        __syncthreads();
    }
    float acc[4][4];
    #pragma unroll
    for (int i = 0; i < 4; i++) {
        unpack2(accp[i][0], acc[i][0], acc[i][1]);
        unpack2(accp[i][1], acc[i][2], acc[i][3]);
    }
    #pragma unroll
    for (int i = 0; i < 4; i++) {
        int m = m0 + ty*4 + i;
        #pragma unroll
        for (int j = 0; j < 4; j++)
            g_P[(m*4 + q)*DD + n0 + tx*4 + j] = acc[i][j];
    }
}

// ---------------- K5a: MLPs + softmax + w outputs + small-path ----------------
__global__ void k_wsoft(const float* __restrict__ dur,
                        const float* __restrict__ Mw, const float* __restrict__ Mc,
                        const float* __restrict__ Lc,
                        const float* __restrict__ lbw, const float* __restrict__ lbc,
                        float* __restrict__ out) {
    int t = blockIdx.x, b = blockIdx.y;
    int tid = threadIdx.x;
    float* w_out = out + W_OFF;
    int fl = g_flen[b];
    if (t >= fl) {
        for (int i = tid; i < 4*LL; i += 256) {
            int q = i / LL, l = i % LL;
            w_out[(((size_t)b*4 + q)*TT + t)*LL + l] = 0.f;
        }
        return;
    }
    __shared__ float s_arr[4*256];
    __shared__ float s_part[8*8];
    __shared__ float s_max[4], s_sum[4], s_wc[8];

    float lw[4], cc[2];
    bool valid = tid < LL;
    float tp1 = (float)(t + 1);
    if (valid) {
        float d = dur[b*LL + tid];
        bool pm = d > 0.f;
        float4 bw = g_bw4[b*LL + tid];
        float2 bc = g_bc2[b*LL + tid];
        float v0 = siluf(bw.x + tp1*Mw[0]);
        float v1 = siluf(bw.y + tp1*Mw[1]);
        float v2 = siluf(bw.z + tp1*Mw[2]);
        float v3 = siluf(bw.w + tp1*Mw[3]);
        lw[0] = pm ? v0 : NEG_INF;
        lw[1] = pm ? v1 : NEG_INF;
        lw[2] = pm ? v2 : NEG_INF;
        lw[3] = pm ? v3 : NEG_INF;
        cc[0] = siluf(bc.x + tp1*Mc[0]);
        cc[1] = siluf(bc.y + tp1*Mc[1]);
    } else {
        lw[0] = lw[1] = lw[2] = lw[3] = NEG_INF;
        cc[0] = cc[1] = 0.f;
    }
    #pragma unroll
    for (int q = 0; q < 4; q++) s_arr[q*256 + tid] = lw[q];
    __syncthreads();
    int wid = tid / 32, lane = tid % 32;
    if (wid < 4) {
        float m = NEG_INF;
        for (int i = lane; i < 256; i += 32) m = fmaxf(m, s_arr[wid*256 + i]);
        #pragma unroll
        for (int off = 16; off > 0; off >>= 1) m = fmaxf(m, __shfl_down_sync(0xffffffffu, m, off));
        if (lane == 0) s_max[wid] = m;
    }
    __syncthreads();
    float ex[4];
    #pragma unroll
    for (int q = 0; q < 4; q++) {
        ex[q] = __expf(lw[q] - s_max[q]);
        s_arr[q*256 + tid] = ex[q];
    }
    __syncthreads();
    if (wid < 4) {
        float sm = 0.f;
        for (int i = lane; i < 256; i += 32) sm += s_arr[wid*256 + i];
        #pragma unroll
        for (int off = 16; off > 0; off >>= 1) sm += __shfl_down_sync(0xffffffffu, sm, off);
        if (lane == 0) s_sum[wid] = sm;
    }
    __syncthreads();
    float wq[4];
    #pragma unroll
    for (int q = 0; q < 4; q++) wq[q] = ex[q] / s_sum[q];
    if (valid) {
        #pragma unroll
        for (int q = 0; q < 4; q++)
            w_out[(((size_t)b*4 + q)*TT + t)*LL + tid] = wq[q];
        float4 v = make_float4(wq[0], wq[1], wq[2], wq[3]);
        *(float4*)&g_Wscr[((size_t)b*TT + t)*800 + tid*4] = v;
    }
    float prod[8];
    #pragma unroll
    for (int q = 0; q < 4; q++)
        #pragma unroll
        for (int p = 0; p < 2; p++) prod[q*2+p] = wq[q]*cc[p];
    #pragma unroll
    for (int j = 0; j < 8; j++) {
        float v = prod[j];
        #pragma unroll
        for (int off = 16; off > 0; off >>= 1) v += __shfl_down_sync(0xffffffffu, v, off);
        if (lane == 0) s_part[wid*8 + j] = v;
    }
    __syncthreads();
    if (tid < 8) {
        float s = 0.f;
        #pragma unroll
        for (int w = 0; w < 8; w++) s += s_part[w*8 + tid];
        s_wc[tid] = s;
    }
    __syncthreads();
    float acc = lbw[tid] + lbc[tid];
    #pragma unroll
    for (int qp = 0; qp < 8; qp++) acc += s_wc[qp]*Lc[qp*DD + tid];
    g_part[((size_t)b*TT + t)*DD + tid] = acc;
}

// ---------------- K5b: whc = W(1000x800) @ P_b(800x256) + part, masked ----------------
__global__ void k_gemm_whc() {
    int nt = blockIdx.x, mt = blockIdx.y, b = blockIdx.z;
    int m0 = mt*64, n0 = nt*64;
    int fl = g_flen[b];
    int tid = threadIdx.x;
    int ty = tid / 16, tx = tid % 16;
    if (m0 >= fl) {
        // entire tile above frame length -> zeros
        #pragma unroll
        for (int i = 0; i < 4; i++) {
            int m = m0 + ty*4 + i;
            if (m < TT)
                #pragma unroll
                for (int j = 0; j < 4; j++)
                    g_whc[((size_t)b*TT + m)*DD + n0 + tx*4 + j] = 0.f;
        }
        return;
    }
    const float* A  = g_Wscr + (size_t)b*TT*800;
    const float* Bm = g_P + (size_t)b*LL*4*DD;
    __shared__ float As[16*64], Bs[16*64];
    int arow = tid / 4, akq = tid % 4;
    int brow = tid / 16, bnq = tid % 16;
    unsigned long long accp[4][2] = {};
    for (int k0 = 0; k0 < 800; k0 += 16) {
        int am = m0 + arow;
        float4 a4 = make_float4(0.f, 0.f, 0.f, 0.f);
        if (am < TT) a4 = *(const float4*)&A[(size_t)am*800 + k0 + akq*4];
        float4 b4 = *(const float4*)&Bm[(k0 + brow)*DD + n0 + bnq*4];
        As[(akq*4+0)*64 + arow] = a4.x;
        As[(akq*4+1)*64 + arow] = a4.y;
        As[(akq*4+2)*64 + arow] = a4.z;
        As[(akq*4+3)*64 + arow] = a4.w;
        *(float4*)&Bs[brow*64 + bnq*4] = b4;
        __syncthreads();
        tile_mma16(As, Bs, ty, tx, accp);
        __syncthreads();
    }
    float acc[4][4];
    #pragma unroll
    for (int i = 0; i < 4; i++) {
        unpack2(accp[i][0], acc[i][0], acc[i][1]);
        unpack2(accp[i][1], acc[i][2], acc[i][3]);
    }
    #pragma unroll
    for (int i = 0; i < 4; i++) {
        int m = m0 + ty*4 + i;
        if (m < TT) {
            #pragma unroll
            for (int j = 0; j < 4; j++) {
                int e = n0 + tx*4 + j;
                float v = (m < fl) ? acc[i][j] + g_part[((size_t)b*TT + m)*DD + e] : 0.f;
                g_whc[((size_t)b*TT + m)*DD + e] = v;
            }
        }
    }
}

// ---------------- K5c: out = whc(16000x256) @ Wo(256x512) + bo, transposed write ----------------
__global__ void k_gemm_out(const float* __restrict__ Wo, const float* __restrict__ bo,
                           float* __restrict__ out) {
    int nt = blockIdx.x, mt = blockIdx.y;
    int m0 = mt*64, n0 = nt*64;
    int tid = threadIdx.x;
    int ty = tid / 16, tx = tid % 16;
    // early-out: whole tile in one batch AND above its frame length -> bias only
    {
        int b0 = m0 / TT, b1 = (m0 + 63) / TT;
        if (b0 == b1 && (m0 - b0*TT) >= g_flen[b0]) {
            #pragma unroll
            for (int j = 0; j < 4; j++) {
                int o = n0 + tx*4 + j;
                float bj = bo[o];
                #pragma unroll
                for (int i = 0; i < 4; i++) {
                    int m = m0 + ty*4 + i;
                    int b = m / TT, t = m % TT;
                    if (o < 256) out[((size_t)b*256 + o)*TT + t] = bj;
                    else         out[LS_OFF + ((size_t)b*256 + (o - 256))*TT + t] = bj;
                }
            }
            return;
        }
    }
    const float* A = g_whc;
    __shared__ float As[16*64], Bs[16*64];
    int arow = tid / 4, akq = tid % 4;
    int brow = tid / 16, bnq = tid % 16;
    unsigned long long accp[4][2] = {};
    for (int k0 = 0; k0 < DD; k0 += 16) {
        float4 a4 = *(const float4*)&A[((size_t)m0 + arow)*DD + k0 + akq*4];
        float4 b4 = *(const float4*)&Wo[(k0 + brow)*512 + n0 + bnq*4];
        As[(akq*4+0)*64 + arow] = a4.x;
        As[(akq*4+1)*64 + arow] = a4.y;
        As[(akq*4+2)*64 + arow] = a4.z;
        As[(akq*4+3)*64 + arow] = a4.w;
        *(float4*)&Bs[brow*64 + bnq*4] = b4;
        __syncthreads();
        tile_mma16(As, Bs, ty, tx, accp);
        __syncthreads();
    }
    float acc[4][4];
    #pragma unroll
    for (int i = 0; i < 4; i++) {
        unpack2(accp[i][0], acc[i][0], acc[i][1]);
        unpack2(accp[i][1], acc[i][2], acc[i][3]);
    }
    #pragma unroll
    for (int j = 0; j < 4; j++) {
        int o = n0 + tx*4 + j;
        float bj = bo[o];
        #pragma unroll
        for (int i = 0; i < 4; i++) {
            int m = m0 + ty*4 + i;
            int b = m / TT, t = m % TT;
            float v = acc[i][j] + bj;
            if (o < 256)
                out[((size_t)b*256 + o)*TT + t] = v;
            else
                out[LS_OFF + ((size_t)b*256 + (o - 256))*TT + t] = v;
        }
    }
}

extern "C" void kernel_launch(void* const* d_in, const int* in_sizes, int n_in,
                              void* d_out, int out_size) {
    const float* dur = (const float*)d_in[0];
    const float* ph  = (const float*)d_in[1];
    const float* Wpw = (const float*)d_in[3];
    const float* bpw = (const float*)d_in[4];
    const float* Cw  = (const float*)d_in[5];
    const float* cbw = (const float*)d_in[6];
    const float* Mw  = (const float*)d_in[7];
    const float* mbw = (const float*)d_in[8];
    const float* Lw  = (const float*)d_in[9];
    const float* lbw = (const float*)d_in[10];
    const float* Wpc = (const float*)d_in[11];
    const float* bpc = (const float*)d_in[12];
    const float* Cc  = (const float*)d_in[13];
    const float* cbc = (const float*)d_in[14];
    const float* Mc  = (const float*)d_in[15];
    const float* mbc = (const float*)d_in[16];
    const float* Lc  = (const float*)d_in[17];
    const float* lbc = (const float*)d_in[18];
    const float* Wo  = (const float*)d_in[19];
    const float* bo  = (const float*)d_in[20];
    float* out = (float*)d_out;

    k_setup<<<BB, 256>>>(dur, out);
    k_fold<<<48, 256>>>(Cw, Wpw, bpw, Cc, Wpc, bpc);
    k_conv<<<BB*LL, 512>>>(ph, dur, cbw, cbc);
    k_base<<<BB, 256>>>(dur, Mw, mbw, Mc, mbc);
    k_transpose<<<dim3(7, 8, BB), dim3(32, 8)>>>(ph);
    k_gemm_P<<<dim3(4, 50, 4), 256>>>(Lw);
    k_wsoft<<<dim3(TT, BB), 256>>>(dur, Mw, Mc, Lc, lbw, lbc, out);
    k_gemm_whc<<<dim3(4, 16, BB), 256>>>();
    k_gemm_out<<<dim3(8, 250), 256>>>(Wo, bo, out);
}